// round 12
// baseline (speedup 1.0000x reference)
#include <cuda_runtime.h>
#include <cuda_bf16.h>
#include <stdint.h>
#include <math.h>

// Problem constants (fixed by setup_inputs)
#define S     2048
#define HID   2048
#define NHEAD 16
#define HDIM  128
#define HDTOT 2048
#define RING_REST 3.0f   // world_size - 1 identical non-causal ring steps

typedef __nv_bfloat16 bf16;

// ---------------- static device scratch (no runtime allocation allowed) ----------------
__device__ bf16  g_Xh [S * HID],     g_Xl [S * HID];
__device__ bf16  g_qwh[HDTOT * HID], g_qwl[HDTOT * HID];
__device__ bf16  g_kwh[HDTOT * HID], g_kwl[HDTOT * HID];
__device__ bf16  g_vwh[HDTOT * HID], g_vwl[HDTOT * HID];
__device__ bf16  g_owh[HID * HDTOT], g_owl[HID * HDTOT];
__device__ bf16  g_qh [S * HDTOT], g_ql [S * HDTOT];
__device__ bf16  g_kh [S * HDTOT], g_kl [S * HDTOT];
__device__ bf16  g_vh [S * HDTOT], g_vl [S * HDTOT];
__device__ bf16  g_vth[HDTOT * S], g_vtl[HDTOT * S];   // V transposed (H*D, S)
__device__ bf16  g_ath[S * HDTOT], g_atl[S * HDTOT];
__device__ float g_scores[(size_t)NHEAD * S * S];      // 256 MB
__device__ bf16  g_wh[(size_t)NHEAD * S * S];          // attention weights hi
__device__ bf16  g_wl[(size_t)NHEAD * S * S];          // attention weights lo

// ---------------- PTX helpers (base compute_103 features only) ----------------
__device__ __forceinline__ uint32_t smem_u32(const void* p) {
    uint32_t a;
    asm("{ .reg .u64 t; cvta.to.shared.u64 t, %1; cvt.u32.u64 %0, t; }" : "=r"(a) : "l"(p));
    return a;
}
__device__ __forceinline__ void cp16(uint32_t s, const void* g) {
    asm volatile("cp.async.cg.shared.global [%0], [%1], 16;" :: "r"(s), "l"(g));
}
#define CP_COMMIT() asm volatile("cp.async.commit_group;" ::: "memory")

#define LDSM4(r, addr) \
    asm volatile("ldmatrix.sync.aligned.m8n8.x4.shared.b16 {%0,%1,%2,%3}, [%4];" \
        : "=r"((r)[0]), "=r"((r)[1]), "=r"((r)[2]), "=r"((r)[3]) : "r"(addr))

#define MMA(cc, aa, b0, b1) \
    asm volatile("mma.sync.aligned.m16n8k16.row.col.f32.bf16.bf16.f32 " \
        "{%0,%1,%2,%3}, {%4,%5,%6,%7}, {%8,%9}, {%0,%1,%2,%3};" \
        : "+f"((cc)[0]), "+f"((cc)[1]), "+f"((cc)[2]), "+f"((cc)[3]) \
        : "r"((aa)[0]), "r"((aa)[1]), "r"((aa)[2]), "r"((aa)[3]), "r"(b0), "r"(b1))

// ---------------- merged split kernel: 5 fp32 tensors -> bf16 hi/lo ----------------
struct SplitArgs {
    const float* s[5];
    bf16* h[5];
    bf16* l[5];
};

__global__ __launch_bounds__(256)
void split5(SplitArgs a) {
    const int set = blockIdx.y;
    const int i = blockIdx.x * 256 + threadIdx.x;     // grid sized exactly
    float4 v = ((const float4*)a.s[set])[i];
    bf16 h0 = __float2bfloat16_rn(v.x), h1 = __float2bfloat16_rn(v.y);
    bf16 h2 = __float2bfloat16_rn(v.z), h3 = __float2bfloat16_rn(v.w);
    bf16 l0 = __float2bfloat16_rn(v.x - __bfloat162float(h0));
    bf16 l1 = __float2bfloat16_rn(v.y - __bfloat162float(h1));
    bf16 l2 = __float2bfloat16_rn(v.z - __bfloat162float(h2));
    bf16 l3 = __float2bfloat16_rn(v.w - __bfloat162float(h3));
    ((__nv_bfloat162*)a.h[set])[2 * i]     = __halves2bfloat162(h0, h1);
    ((__nv_bfloat162*)a.h[set])[2 * i + 1] = __halves2bfloat162(h2, h3);
    ((__nv_bfloat162*)a.l[set])[2 * i]     = __halves2bfloat162(l0, l1);
    ((__nv_bfloat162*)a.l[set])[2 * i + 1] = __halves2bfloat162(l2, l3);
}

// ---------------- bf16 transpose (pure permutation of hi and lo arrays) ----------------
__global__ __launch_bounds__(256)
void transpose_b16(const bf16* __restrict__ sh, const bf16* __restrict__ sl,
                   bf16* __restrict__ th, bf16* __restrict__ tl) {
    __shared__ bf16 t0[32][34];
    __shared__ bf16 t1[32][34];
    int c0 = blockIdx.x * 32, r0 = blockIdx.y * 32;
    int x = threadIdx.x, y = threadIdx.y;   // block (32,8)
#pragma unroll
    for (int i = 0; i < 32; i += 8) {
        size_t o = (size_t)(r0 + y + i) * HDTOT + (c0 + x);
        t0[y + i][x] = sh[o];
        t1[y + i][x] = sl[o];
    }
    __syncthreads();
#pragma unroll
    for (int i = 0; i < 32; i += 8) {
        size_t o = (size_t)(c0 + y + i) * S + (r0 + x);
        th[o] = t0[x][y + i];
        tl[o] = t1[x][y + i];
    }
}

// ---------------- split-bf16 GEMM via mma.sync:  C = alpha*(A*B^T) + bias ----------------
// CTA tile 128x128, BK=32, 8 warps (2m x 4n), 3-stage cp.async pipeline (96KB smem).
// nsets>1: blockIdx.z selects an independent (B, bias, dest) set (A fixed, sAz=0).
// nsets==1: blockIdx.z strides A/B/C by sAz/sBz/sCz (batched heads).
// mode 0: fp32 C.  mode 1: bf16 hi/lo split to Ch/Cl.
#define GEMM_SMEM_BYTES 98304

struct GemmSet {
    const bf16 *Bh, *Bl;
    const float *bias;
    float *C;
    bf16 *Ch, *Cl;
};
struct GemmSets { GemmSet s[3]; };

__global__ __launch_bounds__(256)
void gemm_bf3(const bf16* __restrict__ Ah, const bf16* __restrict__ Al, int lda, long long sAz,
              GemmSets sets, int nsets, int ldb, long long sBz,
              int ldc, long long sCz,
              int K, float alpha, int mode)
{
    extern __shared__ char smdyn[];
    __shared__ float bS[128];
    const uint32_t smb = smem_u32(smdyn);
    const int tid = threadIdx.x, lane = tid & 31, wid = tid >> 5;
    const int m0 = blockIdx.y * 128, n0 = blockIdx.x * 128;
    const int wm = (wid >> 2) * 64, wn = (wid & 3) * 32;

    GemmSet st = sets.s[nsets > 1 ? blockIdx.z : 0];
    Ah += (size_t)blockIdx.z * sAz;
    Al += (size_t)blockIdx.z * sAz;
    if (nsets == 1) {
        st.Bh += (size_t)blockIdx.z * sBz;
        st.Bl += (size_t)blockIdx.z * sBz;
        if (st.C)  st.C  += (size_t)blockIdx.z * sCz;
        if (st.Ch) { st.Ch += (size_t)blockIdx.z * sCz; st.Cl += (size_t)blockIdx.z * sCz; }
    }

    if (tid < 128) bS[tid] = st.bias ? st.bias[n0 + tid] : 0.f;

    // ---- loader mapping: thread -> (row, chunk pair). 512 chunks (16B) per buffer.
    const int idr = tid >> 1;           // row 0..127
    const int idc = (tid & 1) * 2;      // chunk 0 or 2
    const uint32_t swl = (idr >> 1) & 3;
    const uint32_t s0 = idr * 64 + ((idc ^ swl) << 4);
    const uint32_t s1 = idr * 64 + (((idc + 1) ^ swl) << 4);
    const bf16* gAh = Ah + (size_t)(m0 + idr) * lda + idc * 8;
    const bf16* gAl = Al + (size_t)(m0 + idr) * lda + idc * 8;
    const bf16* gBh = st.Bh + (size_t)(n0 + idr) * ldb + idc * 8;
    const bf16* gBl = st.Bl + (size_t)(n0 + idr) * ldb + idc * 8;

#define ISSUE(stg, kt) do {                                                    \
        uint32_t _b = smb + (stg) * 32768;                                     \
        cp16(_b +         s0, gAh + (kt)); cp16(_b +         s1, gAh + (kt) + 8); \
        cp16(_b +  8192 + s0, gAl + (kt)); cp16(_b +  8192 + s1, gAl + (kt) + 8); \
        cp16(_b + 16384 + s0, gBh + (kt)); cp16(_b + 16384 + s1, gBh + (kt) + 8); \
        cp16(_b + 24576 + s0, gBl + (kt)); cp16(_b + 24576 + s1, gBl + (kt) + 8); \
        CP_COMMIT();                                                           \
    } while (0)

    float c[4][4][4];
#pragma unroll
    for (int i = 0; i < 4; ++i)
#pragma unroll
        for (int j = 0; j < 4; ++j)
#pragma unroll
            for (int r = 0; r < 4; ++r) c[i][j][r] = 0.f;

    // lane-fixed pieces of ldmatrix addressing
    const int arow_l = lane & 15;                 // A: row within 16-row tile
    const int achk_l = lane >> 4;                 // A: k-chunk select (0/1)
    const int brow_l = (lane & 7) + ((lane >> 4) << 3);  // B: row within 16-n pair
    const int bchk_l = (lane >> 3) & 1;           // B: k-chunk select (0/1)

    const int nk = K / 32;                        // always >= 4 here
    ISSUE(0, 0);
    ISSUE(1, 32);

    for (int kt = 0; kt < nk; ++kt) {
        if (kt + 2 < nk) {
            ISSUE((kt + 2) % 3, (kt + 2) * 32);
            asm volatile("cp.async.wait_group 2;" ::: "memory");
        } else if (kt + 1 < nk) {
            asm volatile("cp.async.wait_group 1;" ::: "memory");
        } else {
            asm volatile("cp.async.wait_group 0;" ::: "memory");
        }
        __syncthreads();

        const uint32_t base = smb + (kt % 3) * 32768;
#pragma unroll
        for (int kk = 0; kk < 2; ++kk) {          // two k16 halves of BK=32
            const int c0 = kk * 2;
            uint32_t a_h[4][4], a_l[4][4];
            const int ac = c0 + achk_l;
#pragma unroll
            for (int i = 0; i < 4; ++i) {
                int row = wm + i * 16 + arow_l;
                uint32_t ph = row * 64 + ((ac ^ ((row >> 1) & 3)) << 4);
                LDSM4(a_h[i], base + ph);
                LDSM4(a_l[i], base + 8192 + ph);
            }
            uint32_t b_h[4][2], b_l[4][2];
            const int bc = c0 + bchk_l;
#pragma unroll
            for (int j2 = 0; j2 < 2; ++j2) {
                int row = wn + j2 * 16 + brow_l;
                uint32_t ph = row * 64 + ((bc ^ ((row >> 1) & 3)) << 4);
                uint32_t r[4];
                LDSM4(r, base + 16384 + ph);
                b_h[2 * j2][0] = r[0]; b_h[2 * j2][1] = r[1];
                b_h[2 * j2 + 1][0] = r[2]; b_h[2 * j2 + 1][1] = r[3];
                LDSM4(r, base + 24576 + ph);
                b_l[2 * j2][0] = r[0]; b_l[2 * j2][1] = r[1];
                b_l[2 * j2 + 1][0] = r[2]; b_l[2 * j2 + 1][1] = r[3];
            }
#pragma unroll
            for (int i = 0; i < 4; ++i)
#pragma unroll
                for (int j = 0; j < 4; ++j) {
                    MMA(c[i][j], a_h[i], b_h[j][0], b_h[j][1]);
                    MMA(c[i][j], a_h[i], b_l[j][0], b_l[j][1]);
                    MMA(c[i][j], a_l[i], b_h[j][0], b_h[j][1]);
                }
        }
        __syncthreads();
    }

    // ---- epilogue
#pragma unroll
    for (int i = 0; i < 4; ++i) {
        int r0 = m0 + wm + i * 16 + (lane >> 2);
#pragma unroll
        for (int j = 0; j < 4; ++j) {
            int cb = wn + j * 8 + (lane & 3) * 2;
            float b0 = bS[cb], b1 = bS[cb + 1];
            float x0 = c[i][j][0] * alpha + b0, x1 = c[i][j][1] * alpha + b1;
            float x2 = c[i][j][2] * alpha + b0, x3 = c[i][j][3] * alpha + b1;
            if (mode == 0) {
                float2 v0 = { x0, x1 }, v1 = { x2, x3 };
                *(float2*)&st.C[(size_t)r0 * ldc + n0 + cb] = v0;
                *(float2*)&st.C[(size_t)(r0 + 8) * ldc + n0 + cb] = v1;
            } else {
                bf16 h0 = __float2bfloat16_rn(x0), h1 = __float2bfloat16_rn(x1);
                bf16 h2 = __float2bfloat16_rn(x2), h3 = __float2bfloat16_rn(x3);
                *(__nv_bfloat162*)&st.Ch[(size_t)r0 * ldc + n0 + cb] = __halves2bfloat162(h0, h1);
                *(__nv_bfloat162*)&st.Cl[(size_t)r0 * ldc + n0 + cb] = __halves2bfloat162(
                    __float2bfloat16_rn(x0 - __bfloat162float(h0)),
                    __float2bfloat16_rn(x1 - __bfloat162float(h1)));
                *(__nv_bfloat162*)&st.Ch[(size_t)(r0 + 8) * ldc + n0 + cb] = __halves2bfloat162(h2, h3);
                *(__nv_bfloat162*)&st.Cl[(size_t)(r0 + 8) * ldc + n0 + cb] = __halves2bfloat162(
                    __float2bfloat16_rn(x2 - __bfloat162float(h2)),
                    __float2bfloat16_rn(x3 - __bfloat162float(h3)));
            }
        }
    }
#undef ISSUE
}

// ---------------- ring-softmax: scores(fp32) -> combined weights (bf16 hi/lo) ----------------
__global__ __launch_bounds__(256)
void ring_softmax(const float* __restrict__ scores, bf16* __restrict__ wh, bf16* __restrict__ wl)
{
    const int row = blockIdx.x;
    const size_t off = ((size_t)blockIdx.y * S + row) * S;
    const float* p = scores + off;
    const int tid = threadIdx.x;

    float v[8];
    float mB = -3.0e38f, mC = -3.0e38f;
#pragma unroll
    for (int t = 0; t < 8; ++t) {
        int j = t * 256 + tid;
        v[t] = p[j];
        mB = fmaxf(mB, v[t]);
        if (j <= row) mC = fmaxf(mC, v[t]);
    }

    __shared__ float sm0[8], sm1[8];
    const int wid = tid >> 5, lid = tid & 31;
#pragma unroll
    for (int o = 16; o > 0; o >>= 1) {
        mB = fmaxf(mB, __shfl_xor_sync(0xffffffffu, mB, o));
        mC = fmaxf(mC, __shfl_xor_sync(0xffffffffu, mC, o));
    }
    if (lid == 0) { sm0[wid] = mB; sm1[wid] = mC; }
    __syncthreads();
    mB = sm0[0]; mC = sm1[0];
#pragma unroll
    for (int i = 1; i < 8; ++i) { mB = fmaxf(mB, sm0[i]); mC = fmaxf(mC, sm1[i]); }
    __syncthreads();

    float eb[8], ec[8];
    float sB = 0.f, sC = 0.f;
#pragma unroll
    for (int t = 0; t < 8; ++t) {
        int j = t * 256 + tid;
        eb[t] = __expf(v[t] - mB);
        ec[t] = (j <= row) ? __expf(v[t] - mC) : 0.f;
        sB += eb[t];
        sC += ec[t];
    }
#pragma unroll
    for (int o = 16; o > 0; o >>= 1) {
        sB += __shfl_xor_sync(0xffffffffu, sB, o);
        sC += __shfl_xor_sync(0xffffffffu, sC, o);
    }
    if (lid == 0) { sm0[wid] = sB; sm1[wid] = sC; }
    __syncthreads();
    sB = 0.f; sC = 0.f;
#pragma unroll
    for (int i = 0; i < 8; ++i) { sB += sm0[i]; sC += sm1[i]; }

    const float e     = __expf(mC - mB);
    const float cb    = RING_REST / (sB + 1e-8f);
    const float cc    = e / (sC + 1e-8f);
    const float invSe = 1.0f / (e * sC + RING_REST * sB + 1e-8f);
#pragma unroll
    for (int t = 0; t < 8; ++t) {
        int j = t * 256 + tid;
        float w = (eb[t] * cb + ec[t] * cc) * invSe;
        bf16 h = __float2bfloat16_rn(w);
        wh[off + j] = h;
        wl[off + j] = __float2bfloat16_rn(w - __bfloat162float(h));
    }
}

// ---------------- launch ----------------
extern "C" void kernel_launch(void* const* d_in, const int* in_sizes, int n_in,
                              void* d_out, int out_size)
{
    (void)in_sizes; (void)n_in; (void)out_size;
    const float* X  = (const float*)d_in[0];
    const float* qw = (const float*)d_in[1];
    const float* qb = (const float*)d_in[2];
    const float* kw = (const float*)d_in[3];
    const float* kb = (const float*)d_in[4];
    const float* vw = (const float*)d_in[5];
    const float* vb = (const float*)d_in[6];
    const float* ow = (const float*)d_in[7];
    const float* ob = (const float*)d_in[8];
    float* out = (float*)d_out;

    bf16 *xh, *xl, *qwh, *qwl, *kwh, *kwl, *vwh, *vwl, *owh, *owl;
    bf16 *qh, *ql, *kh, *kl, *vh, *vl, *vth, *vtl, *ath, *atl, *wh, *wl;
    float *gs;
    cudaGetSymbolAddress((void**)&xh,  g_Xh);  cudaGetSymbolAddress((void**)&xl,  g_Xl);
    cudaGetSymbolAddress((void**)&qwh, g_qwh); cudaGetSymbolAddress((void**)&qwl, g_qwl);
    cudaGetSymbolAddress((void**)&kwh, g_kwh); cudaGetSymbolAddress((void**)&kwl, g_kwl);
    cudaGetSymbolAddress((void**)&vwh, g_vwh); cudaGetSymbolAddress((void**)&vwl, g_vwl);
    cudaGetSymbolAddress((void**)&owh, g_owh); cudaGetSymbolAddress((void**)&owl, g_owl);
    cudaGetSymbolAddress((void**)&qh,  g_qh);  cudaGetSymbolAddress((void**)&ql,  g_ql);
    cudaGetSymbolAddress((void**)&kh,  g_kh);  cudaGetSymbolAddress((void**)&kl,  g_kl);
    cudaGetSymbolAddress((void**)&vh,  g_vh);  cudaGetSymbolAddress((void**)&vl,  g_vl);
    cudaGetSymbolAddress((void**)&vth, g_vth); cudaGetSymbolAddress((void**)&vtl, g_vtl);
    cudaGetSymbolAddress((void**)&ath, g_ath); cudaGetSymbolAddress((void**)&atl, g_atl);
    cudaGetSymbolAddress((void**)&gs,  g_scores);
    cudaGetSymbolAddress((void**)&wh,  g_wh);  cudaGetSymbolAddress((void**)&wl,  g_wl);

    cudaFuncSetAttribute(gemm_bf3, cudaFuncAttributeMaxDynamicSharedMemorySize, GEMM_SMEM_BYTES);

    const float scale = 0.08838834764831843f;   // 1/sqrt(128)
    dim3 gblk(256);

    // split inputs + weights to bf16 hi/lo (single launch, 5 sets)
    {
        SplitArgs sa;
        sa.s[0] = X;  sa.h[0] = xh;  sa.l[0] = xl;
        sa.s[1] = qw; sa.h[1] = qwh; sa.l[1] = qwl;
        sa.s[2] = kw; sa.h[2] = kwh; sa.l[2] = kwl;
        sa.s[3] = vw; sa.h[3] = vwh; sa.l[3] = vwl;
        sa.s[4] = ow; sa.h[4] = owh; sa.l[4] = owl;
        split5<<<dim3(S * HID / 4 / 256, 5), dim3(256)>>>(sa);
    }

    // merged Q/K/V projections -> split bf16 (one launch, z selects weight set)
    {
        GemmSets gsz = {};
        gsz.s[0] = { qwh, qwl, qb, nullptr, qh, ql };
        gsz.s[1] = { kwh, kwl, kb, nullptr, kh, kl };
        gsz.s[2] = { vwh, vwl, vb, nullptr, vh, vl };
        gemm_bf3<<<dim3(16, 16, 3), gblk, GEMM_SMEM_BYTES>>>(
            xh, xl, HID, 0, gsz, 3, HID, 0, HDTOT, 0, HID, 1.0f, 1);
    }

    // transpose V hi/lo (pure bf16 permutation)
    transpose_b16<<<dim3(HDTOT / 32, S / 32), dim3(32, 8)>>>(vh, vl, vth, vtl);

    // scores[h] = scale * Q_h @ K_h^T  (fp32 out for softmax precision)
    {
        GemmSets gsz = {};
        gsz.s[0] = { kh, kl, nullptr, gs, nullptr, nullptr };
        gemm_bf3<<<dim3(16, 16, NHEAD), gblk, GEMM_SMEM_BYTES>>>(
            qh, ql, HDTOT, HDIM, gsz, 1, HDTOT, HDIM,
            S, (long long)S * S, HDIM, scale, 0);
    }

    // combined ring softmax -> bf16 hi/lo weights
    ring_softmax<<<dim3(S, NHEAD), dim3(256)>>>(gs, wh, wl);

    // attn[h] = W_h @ V_h -> split bf16 directly
    {
        GemmSets gsz = {};
        gsz.s[0] = { vth, vtl, nullptr, nullptr, ath, atl };
        gemm_bf3<<<dim3(1, 16, NHEAD), gblk, GEMM_SMEM_BYTES>>>(
            wh, wl, S, (long long)S * S, gsz, 1, S, (long long)HDIM * S,
            HDTOT, HDIM, S, 1.0f, 1);
    }

    // output projection (fp32 to d_out)
    {
        GemmSets gsz = {};
        gsz.s[0] = { owh, owl, ob, out, nullptr, nullptr };
        gemm_bf3<<<dim3(16, 16, 1), gblk, GEMM_SMEM_BYTES>>>(
            ath, atl, HDTOT, 0, gsz, 1, HDTOT, 0, HID, 0, HDTOT, 1.0f, 0);
    }
}